// round 7
// baseline (speedup 1.0000x reference)
#include <cuda_runtime.h>

#define W    128
#define HW   16384          // 128*128
#define C    192
#define C2   96             // C/2 float2
#define C4   48             // C/4 float4

// ---- scratch (no allocations allowed) ----
__device__ __align__(16) float g_in_t[HW * C];    // input, pixel-major [p][c]
__device__ __align__(16) float g_ref_t[HW * C];   // ref,   pixel-major [p][c]
__device__ int g_pos[2][HW];                      // ping-pong packed match: y*W+x

// random-search offset tables (candidate order matches reference)
__constant__ int XOFF9[9] = {-1, 0, 1, -1, 0, 1, -1, 0, 1};
__constant__ int YOFF9[9] = {-1,-1,-1,  0, 0, 0,  1, 1, 1};
__constant__ int DX9[9]   = { 0,-1,-1,  0, 0, 0,  1, 1, 0};
__constant__ int DY9[9]   = { 1, 0, 0,  1, 0,-1,  0, 0,-1};

__device__ __forceinline__ int refl(int t) {
    t = (t < 0) ? -t : t;                 // single reflection valid: |shift| <= 64 < 128
    return (t >= W) ? (2 * W - 2 - t) : t;
}

// ---- tiled transpose: in [C][HW] -> out [HW][C] ----
__global__ void transpose_k(const float* __restrict__ in, float* __restrict__ out) {
    __shared__ float tile[32][33];
    const int pb = blockIdx.x * 32;       // pixel block
    const int cb = blockIdx.y * 32;       // channel block
    const int tx = threadIdx.x, ty = threadIdx.y;   // 32 x 8
#pragma unroll
    for (int i = 0; i < 32; i += 8)
        tile[ty + i][tx] = in[(cb + ty + i) * HW + pb + tx];
    __syncthreads();
#pragma unroll
    for (int i = 0; i < 32; i += 8)
        out[(pb + ty + i) * C + cb + tx] = tile[tx][ty + i];
}

// ---- init packed field from float inputs ----
__global__ void init_k(const float* __restrict__ xf, const float* __restrict__ yf) {
    int p = blockIdx.x * 256 + threadIdx.x;
    if (p < HW)
        g_pos[0][p] = ((int)yf[p]) * W + (int)xf[p];
}

// ---- one evaluate step ----
// Block = 192 threads = 2 pixels x 3 warps; each warp handles 3 of the pixel's
// 9 candidates with 32 lanes (float2 per lane). Low regs => high occupancy,
// 6x more warps than the 2-pixel-per-warp version.
// MODE 0: propagation (dilated reflect-padded neighbor shifts)
// MODE 1: random search (jittered offsets around own match)
template <int MODE>
__global__ __launch_bounds__(192, 8) void eval_k(int src, int k, int m) {
    __shared__ float s_sum[2][9];
    __shared__ int   s_cand[2][9];

    const int warp = threadIdx.x >> 5;      // 0..5
    const int lane = threadIdx.x & 31;
    const int pix  = warp / 3;              // pixel slot in block: 0..1
    const int cg   = warp - pix * 3;        // candidate group: 0..2
    const int p    = blockIdx.x * 2 + pix;
    const int y = p >> 7, x = p & 127;

    const float2* __restrict__ inp = reinterpret_cast<const float2*>(g_in_t) + (size_t)p * C2;
    const float2 a0 = inp[lane];
    const float2 a1 = inp[lane + 32];
    const float2 a2 = inp[lane + 64];

    const int* __restrict__ cur = g_pos[src];

    int cand[3];                            // this warp's 3 packed candidates
    if (MODE == 0) {
        const int sy = refl(y + k * (cg - 1));      // c/3 - 1 == cg - 1
#pragma unroll
        for (int j = 0; j < 3; j++) {
            const int sx = refl(x + k * (j - 1));   // c%3 - 1 == j - 1
            cand[j] = __ldg(&cur[sy * W + sx]);
        }
    } else {
        const int v0 = __ldg(&cur[p]);
        const int x0 = v0 & (W - 1), y0 = v0 >> 7;
#pragma unroll
        for (int j = 0; j < 3; j++) {
            const int c  = cg * 3 + j;
            const int cx = (x0 + k * XOFF9[c] + m * DX9[c] + W) & (W - 1);
            const int cy = (y0 + k * YOFF9[c] + m * DY9[c] + W) & (W - 1);
            cand[j] = cy * W + cx;
        }
    }

    // 3 dot products; identical lane/op pattern for every candidate =>
    // duplicate candidates give bitwise-equal sums => strict-> first-wins
    // argmax below matches jnp.argmax exactly.
    float s[3];
    const float2* __restrict__ refb = reinterpret_cast<const float2*>(g_ref_t);
#pragma unroll
    for (int j = 0; j < 3; j++) {
        const float2* r = refb + (size_t)cand[j] * C2;
        const float2 r0 = __ldg(&r[lane]);
        const float2 r1 = __ldg(&r[lane + 32]);
        const float2 r2 = __ldg(&r[lane + 64]);
        s[j] = a0.x * r0.x + a0.y * r0.y
             + a1.x * r1.x + a1.y * r1.y
             + a2.x * r2.x + a2.y * r2.y;
    }

#pragma unroll
    for (int j = 0; j < 3; j++) {
#pragma unroll
        for (int o = 16; o; o >>= 1)
            s[j] += __shfl_xor_sync(0xffffffffu, s[j], o);
    }

    if (lane == 0) {
#pragma unroll
        for (int j = 0; j < 3; j++) {
            s_sum[pix][cg * 3 + j]  = s[j];
            s_cand[pix][cg * 3 + j] = cand[j];
        }
    }
    __syncthreads();

    // one thread per pixel: ordered strict-> argmax over the 9 candidates
    if ((threadIdx.x % 96) == 0) {
        const int q = threadIdx.x / 96;     // 0..1
        float bs = s_sum[q][0];
        int   bp = s_cand[q][0];
#pragma unroll
        for (int c = 1; c < 9; c++)
            if (s_sum[q][c] > bs) { bs = s_sum[q][c]; bp = s_cand[q][c]; }
        g_pos[1 - src][blockIdx.x * 2 + q] = bp;
    }
}

// ---- final: out[0:HW] = (float)(y*W+x), out[HW:2HW] = S (single-candidate dot) ----
__global__ __launch_bounds__(256) void final_k(int src, float* __restrict__ out) {
    const int tid = blockIdx.x * 256 + threadIdx.x;
    const int p   = tid >> 4;
    const int l   = threadIdx.x & 15;

    const int v0 = g_pos[src][p];

    const float4* __restrict__ inp = reinterpret_cast<const float4*>(g_in_t) + (size_t)p * C4;
    const float4* __restrict__ r   = reinterpret_cast<const float4*>(g_ref_t) + (size_t)v0 * C4;

    const float4 a0 = inp[l],      r0 = __ldg(&r[l]);
    const float4 a1 = inp[l + 16], r1 = __ldg(&r[l + 16]);
    const float4 a2 = inp[l + 32], r2 = __ldg(&r[l + 32]);

    float s = a0.x * r0.x + a0.y * r0.y + a0.z * r0.z + a0.w * r0.w
            + a1.x * r1.x + a1.y * r1.y + a1.z * r1.z + a1.w * r1.w
            + a2.x * r2.x + a2.y * r2.y + a2.z * r2.z + a2.w * r2.w;
#pragma unroll
    for (int o = 8; o; o >>= 1)
        s += __shfl_xor_sync(0xffffffffu, s, o);

    if (l == 0) {
        out[p]      = (float)v0;   // max_idx = y*W+x (exact in fp32: < 16384)
        out[HW + p] = s;           // S
    }
}

extern "C" void kernel_launch(void* const* d_in, const int* in_sizes, int n_in,
                              void* d_out, int out_size) {
    const float* input_map = (const float*)d_in[0];
    const float* ref_map   = (const float*)d_in[1];
    const float* irx       = (const float*)d_in[2];
    const float* iry       = (const float*)d_in[3];
    float* out = (float*)d_out;

    float *in_t_p = nullptr, *ref_t_p = nullptr;
    cudaGetSymbolAddress((void**)&in_t_p,  g_in_t);
    cudaGetSymbolAddress((void**)&ref_t_p, g_ref_t);

    // pixel-major transposes (one-time; both maps then live in L2 for all passes)
    dim3 tb(32, 8);
    transpose_k<<<dim3(HW / 32, C / 32), tb>>>(input_map, in_t_p);
    transpose_k<<<dim3(HW / 32, C / 32), tb>>>(ref_map,   ref_t_p);
    init_k<<<HW / 256, 256>>>(irx, iry);

    // setup_inputs is fixed: iteration_count=2, input_minWH=ref_minWH=127, is_final=1
    const int EVAL_BLOCKS = HW / 2;   // 8192 blocks: 2 pixels x 3 warps each
    int src = 0;
    for (int it = 0; it < 2; it++) {
        for (int k = 1; k <= 127; k <<= 1) {            // propagation: k = 1..64
            eval_k<0><<<EVAL_BLOCKS, 192>>>(src, k, 0);
            src ^= 1;
        }
        for (int k = 1; k <= 127; k <<= 1) {            // random search: k = 1..64
            eval_k<1><<<EVAL_BLOCKS, 192>>>(src, k, it % k);
            src ^= 1;
        }
    }
    final_k<<<(HW * 16) / 256, 256>>>(src, out);
}

// round 10
// speedup vs baseline: 1.3585x; 1.3585x over previous
#include <cuda_runtime.h>

#define W    128
#define HW   16384          // 128*128
#define C    192
#define C4   48             // C/4 float4

// ---- scratch (no allocations allowed) ----
__device__ __align__(16) float g_in_t[HW * C];    // input, pixel-major [p][c]
__device__ __align__(16) float g_ref_t[HW * C];   // ref,   pixel-major [p][c]
__device__ int g_pos[2][HW];                      // ping-pong packed match: y*W+x

// random-search offset tables (candidate order matches reference)
__constant__ int XOFF9[9] = {-1, 0, 1, -1, 0, 1, -1, 0, 1};
__constant__ int YOFF9[9] = {-1,-1,-1,  0, 0, 0,  1, 1, 1};
__constant__ int DX9[9]   = { 0,-1,-1,  0, 0, 0,  1, 1, 0};
__constant__ int DY9[9]   = { 1, 0, 0,  1, 0,-1,  0, 0,-1};

__device__ __forceinline__ int refl(int t) {
    t = (t < 0) ? -t : t;                 // single reflection valid: |shift| <= 64 < 128
    return (t >= W) ? (2 * W - 2 - t) : t;
}

// ---- tiled transpose: in [C][HW] -> out [HW][C] ----
__global__ void transpose_k(const float* __restrict__ in, float* __restrict__ out) {
    __shared__ float tile[32][33];
    const int pb = blockIdx.x * 32;       // pixel block
    const int cb = blockIdx.y * 32;       // channel block
    const int tx = threadIdx.x, ty = threadIdx.y;   // 32 x 8
#pragma unroll
    for (int i = 0; i < 32; i += 8)
        tile[ty + i][tx] = in[(cb + ty + i) * HW + pb + tx];
    __syncthreads();
#pragma unroll
    for (int i = 0; i < 32; i += 8)
        out[(pb + ty + i) * C + cb + tx] = tile[tx][ty + i];
}

// ---- init packed field from float inputs ----
__global__ void init_k(const float* __restrict__ xf, const float* __restrict__ yf) {
    int p = blockIdx.x * 256 + threadIdx.x;
    if (p < HW)
        g_pos[0][p] = ((int)yf[p]) * W + (int)xf[p];
}

// ---- one evaluate step: 2 pixels per warp (16 lanes each), float4 gathers ----
// __launch_bounds__(256, 2): 128-reg budget so ptxas can front-batch the 27
// in-flight float4 gathers (R5 showed a 64-reg cap serializing them).
// MODE 0: propagation (dilated reflect-padded neighbor shifts)
// MODE 1: random search (jittered offsets around own match)
template <int MODE>
__global__ __launch_bounds__(256, 2) void eval_k(int src, int k, int m) {
    const int tid = blockIdx.x * 256 + threadIdx.x;
    const int p   = tid >> 4;              // pixel id (16 lanes per pixel)
    const int l   = threadIdx.x & 15;      // lane within pixel group
    const int y = p >> 7, x = p & 127;

    const float4* __restrict__ inp = reinterpret_cast<const float4*>(g_in_t) + (size_t)p * C4;
    const float4 a0 = inp[l];
    const float4 a1 = inp[l + 16];
    const float4 a2 = inp[l + 32];

    const int* __restrict__ cur = g_pos[src];

    int cand[9];                            // packed candidate positions
    if (MODE == 0) {
#pragma unroll
        for (int c = 0; c < 9; c++) {
            const int sy = refl(y + k * (c / 3 - 1));
            const int sx = refl(x + k * (c % 3 - 1));
            cand[c] = __ldg(&cur[sy * W + sx]);
        }
    } else {
        const int v0 = __ldg(&cur[p]);
        const int x0 = v0 & (W - 1), y0 = v0 >> 7;
#pragma unroll
        for (int c = 0; c < 9; c++) {
            const int cx = (x0 + k * XOFF9[c] + m * DX9[c] + W) & (W - 1);
            const int cy = (y0 + k * YOFF9[c] + m * DY9[c] + W) & (W - 1);
            cand[c] = cy * W + cx;
        }
    }

    // 9 dot products; identical summation order per candidate => duplicate
    // candidates produce bitwise-equal sums => first-wins tie-break == argmax.
    float s[9];
    const float4* __restrict__ refb = reinterpret_cast<const float4*>(g_ref_t);
#pragma unroll
    for (int c = 0; c < 9; c++) {
        const float4* r = refb + (size_t)cand[c] * C4;
        const float4 r0 = __ldg(&r[l]);
        const float4 r1 = __ldg(&r[l + 16]);
        const float4 r2 = __ldg(&r[l + 32]);
        s[c] = a0.x * r0.x + a0.y * r0.y + a0.z * r0.z + a0.w * r0.w
             + a1.x * r1.x + a1.y * r1.y + a1.z * r1.z + a1.w * r1.w
             + a2.x * r2.x + a2.y * r2.y + a2.z * r2.z + a2.w * r2.w;
    }

    // reduce within each 16-lane half (xor offsets < 16 stay inside the half)
#pragma unroll
    for (int c = 0; c < 9; c++) {
#pragma unroll
        for (int o = 8; o; o >>= 1)
            s[c] += __shfl_xor_sync(0xffffffffu, s[c], o);
    }

    if (l == 0) {
        float bs = s[0];
        int bp = cand[0];
#pragma unroll
        for (int c = 1; c < 9; c++)
            if (s[c] > bs) { bs = s[c]; bp = cand[c]; }
        g_pos[1 - src][p] = bp;
    }
}

// ---- final: out[0:HW] = (float)(y*W+x), out[HW:2HW] = S (single-candidate dot) ----
__global__ __launch_bounds__(256) void final_k(int src, float* __restrict__ out) {
    const int tid = blockIdx.x * 256 + threadIdx.x;
    const int p   = tid >> 4;
    const int l   = threadIdx.x & 15;

    const int v0 = g_pos[src][p];

    const float4* __restrict__ inp = reinterpret_cast<const float4*>(g_in_t) + (size_t)p * C4;
    const float4* __restrict__ r   = reinterpret_cast<const float4*>(g_ref_t) + (size_t)v0 * C4;

    const float4 a0 = inp[l],      r0 = __ldg(&r[l]);
    const float4 a1 = inp[l + 16], r1 = __ldg(&r[l + 16]);
    const float4 a2 = inp[l + 32], r2 = __ldg(&r[l + 32]);

    float s = a0.x * r0.x + a0.y * r0.y + a0.z * r0.z + a0.w * r0.w
            + a1.x * r1.x + a1.y * r1.y + a1.z * r1.z + a1.w * r1.w
            + a2.x * r2.x + a2.y * r2.y + a2.z * r2.z + a2.w * r2.w;
#pragma unroll
    for (int o = 8; o; o >>= 1)
        s += __shfl_xor_sync(0xffffffffu, s, o);

    if (l == 0) {
        out[p]      = (float)v0;   // max_idx = y*W+x (exact in fp32: < 16384)
        out[HW + p] = s;           // S
    }
}

extern "C" void kernel_launch(void* const* d_in, const int* in_sizes, int n_in,
                              void* d_out, int out_size) {
    const float* input_map = (const float*)d_in[0];
    const float* ref_map   = (const float*)d_in[1];
    const float* irx       = (const float*)d_in[2];
    const float* iry       = (const float*)d_in[3];
    float* out = (float*)d_out;

    float *in_t_p = nullptr, *ref_t_p = nullptr;
    cudaGetSymbolAddress((void**)&in_t_p,  g_in_t);
    cudaGetSymbolAddress((void**)&ref_t_p, g_ref_t);

    // pixel-major transposes (one-time; both maps then live in L2 for all passes)
    dim3 tb(32, 8);
    transpose_k<<<dim3(HW / 32, C / 32), tb>>>(input_map, in_t_p);
    transpose_k<<<dim3(HW / 32, C / 32), tb>>>(ref_map,   ref_t_p);
    init_k<<<HW / 256, 256>>>(irx, iry);

    // setup_inputs is fixed: iteration_count=2, input_minWH=ref_minWH=127, is_final=1
    const int EVAL_BLOCKS = (HW * 16) / 256;   // 1024 blocks: 16 threads per pixel
    int src = 0;
    for (int it = 0; it < 2; it++) {
        for (int k = 1; k <= 127; k <<= 1) {            // propagation: k = 1..64
            eval_k<0><<<EVAL_BLOCKS, 256>>>(src, k, 0);
            src ^= 1;
        }
        for (int k = 1; k <= 127; k <<= 1) {            // random search: k = 1..64
            eval_k<1><<<EVAL_BLOCKS, 256>>>(src, k, it % k);
            src ^= 1;
        }
    }
    final_k<<<(HW * 16) / 256, 256>>>(src, out);
}